// round 6
// baseline (speedup 1.0000x reference)
#include <cuda_runtime.h>
#include <cuda_fp16.h>
#include <cstdint>

// y = x @ W^T,  W[o,k] = scales[o,k/32] * (codes[o,k] - 128)
// R6: merged prepass -> f16 scratch; HMMA GEMM CTA 128x128, 8 warps of
// 32x64, cp.async 3-stage pipeline, SW128-style swizzle, ldmatrix,
// f32 accumulate, __launch_bounds__(256,2) to force 2 CTAs/SM (16 warps).

#define IN_DIM   4096
#define OUT_DIM  4096
#define M_DIM    4096
#define NBLK_    128

#define BM       128
#define BN       128
#define BK       64
#define STAGES   3
#define THREADS  256
#define KITERS   (IN_DIM / BK)   // 64

__device__ __half g_xh[(size_t)M_DIM * IN_DIM];
__device__ __half g_wh[(size_t)OUT_DIM * IN_DIM];

#define A_STAGE_H   (BM * BK)                     // 8192 halves (16 KB)
#define B_STAGE_H   (BN * BK)
#define B_BASE_H    (STAGES * A_STAGE_H)
#define SMEM_BYTES  ((STAGES * (A_STAGE_H + B_STAGE_H)) * 2)   // 98304

// ---------------- merged prepass ----------------
#define NX4 ((M_DIM * IN_DIM) / 4)
#define NW4 ((OUT_DIM * IN_DIM) / 4)

__global__ void prepass_kernel(const float4* __restrict__ x,
                               const float* __restrict__ scales,
                               const int4* __restrict__ codes) {
    int i = blockIdx.x * blockDim.x + threadIdx.x;
    if (i < NX4) {
        float4 v = x[i];
        __half2 h0 = __floats2half2_rn(v.x, v.y);
        __half2 h1 = __floats2half2_rn(v.z, v.w);
        uint2 u;
        u.x = *reinterpret_cast<uint32_t*>(&h0);
        u.y = *reinterpret_cast<uint32_t*>(&h1);
        reinterpret_cast<uint2*>(g_xh)[i] = u;
    } else if (i < NX4 + NW4) {
        int j = i - NX4;
        int gelt = j * 4;
        int o  = gelt >> 12;
        int kb = (gelt & 4095) >> 5;
        float s = __ldg(scales + o * NBLK_ + kb);
        int4 c = codes[j];
        __half2 h0 = __floats2half2_rn(s * (float)(c.x - 128), s * (float)(c.y - 128));
        __half2 h1 = __floats2half2_rn(s * (float)(c.z - 128), s * (float)(c.w - 128));
        uint2 u;
        u.x = *reinterpret_cast<uint32_t*>(&h0);
        u.y = *reinterpret_cast<uint32_t*>(&h1);
        reinterpret_cast<uint2*>(g_wh)[j] = u;
    }
}

// ---------------- GEMM helpers ----------------

__device__ __forceinline__ void cp_async16(uint32_t saddr, const void* g) {
    asm volatile("cp.async.cg.shared.global [%0], [%1], 16;" :: "r"(saddr), "l"(g));
}
__device__ __forceinline__ void cp_commit() {
    asm volatile("cp.async.commit_group;");
}
template <int N>
__device__ __forceinline__ void cp_wait() {
    asm volatile("cp.async.wait_group %0;" :: "n"(N));
}
__device__ __forceinline__ void ldsm_x4(uint32_t& r0, uint32_t& r1,
                                        uint32_t& r2, uint32_t& r3, uint32_t addr) {
    asm volatile("ldmatrix.sync.aligned.m8n8.x4.shared.b16 {%0,%1,%2,%3}, [%4];"
                 : "=r"(r0), "=r"(r1), "=r"(r2), "=r"(r3) : "r"(addr));
}
__device__ __forceinline__ void mma_f16(float* c, const uint32_t* a, const uint32_t* b) {
    asm volatile(
        "mma.sync.aligned.m16n8k16.row.col.f32.f16.f16.f32 "
        "{%0,%1,%2,%3}, {%4,%5,%6,%7}, {%8,%9}, {%0,%1,%2,%3};"
        : "+f"(c[0]), "+f"(c[1]), "+f"(c[2]), "+f"(c[3])
        : "r"(a[0]), "r"(a[1]), "r"(a[2]), "r"(a[3]), "r"(b[0]), "r"(b[1]));
}

__device__ __forceinline__ int tile_off(int row, int chunk) {
    return row * BK + ((chunk ^ (row & 7)) << 3);
}

__device__ __forceinline__ void load_stage(int kb, int st, int m0, int n0,
                                           int tid, uint32_t smem_u32) {
    const __half* gA = g_xh + (size_t)m0 * IN_DIM + kb * BK;
    const __half* gB = g_wh + (size_t)n0 * IN_DIM + kb * BK;
    uint32_t aBase = smem_u32 + (uint32_t)(st * A_STAGE_H) * 2;
    uint32_t bBase = smem_u32 + (uint32_t)(B_BASE_H + st * B_STAGE_H) * 2;
    #pragma unroll
    for (int it = 0; it < 4; it++) {      // A: 128 rows x 8 chunks
        int idx = tid + it * THREADS;
        int row = idx >> 3, ch = idx & 7;
        cp_async16(aBase + (uint32_t)tile_off(row, ch) * 2,
                   gA + (size_t)row * IN_DIM + ch * 8);
    }
    #pragma unroll
    for (int it = 0; it < 4; it++) {      // B: 128 rows x 8 chunks
        int idx = tid + it * THREADS;
        int row = idx >> 3, ch = idx & 7;
        cp_async16(bBase + (uint32_t)tile_off(row, ch) * 2,
                   gB + (size_t)row * IN_DIM + ch * 8);
    }
}

__global__ __launch_bounds__(THREADS, 2)
void gguf_hgemm4(float* __restrict__ y) {
    extern __shared__ __half sm[];
    uint32_t smem_u32 = (uint32_t)__cvta_generic_to_shared(sm);

    const int tid  = threadIdx.x;
    const int lane = tid & 31;
    const int wid  = tid >> 5;
    const int wm   = wid >> 1;     // 0..3 -> 32 m rows each
    const int wn   = wid & 1;      // 0..1 -> 64 n cols each

    const int m0 = blockIdx.y * BM;
    const int n0 = blockIdx.x * BN;

    float acc[2][8][4];
    #pragma unroll
    for (int i = 0; i < 2; i++)
        #pragma unroll
        for (int j = 0; j < 8; j++)
            #pragma unroll
            for (int v = 0; v < 4; v++) acc[i][j][v] = 0.0f;

    const int a_lr = lane & 15;
    const int a_lc = lane >> 4;
    const int b_lr = (lane & 7) + ((lane >> 4) << 3);
    const int b_lc = (lane >> 3) & 1;

    int rowA[2], rowB[4];
    #pragma unroll
    for (int mt = 0; mt < 2; mt++) rowA[mt] = wm * 32 + mt * 16 + a_lr;
    #pragma unroll
    for (int p = 0; p < 4; p++)    rowB[p]  = wn * 64 + p * 16 + b_lr;

    load_stage(0, 0, m0, n0, tid, smem_u32); cp_commit();
    load_stage(1, 1, m0, n0, tid, smem_u32); cp_commit();
    cp_wait<1>();
    __syncthreads();

    int st = 0;
    for (int kb = 0; kb < KITERS; kb++) {
        int nxt = kb + 2;
        if (nxt < KITERS) load_stage(nxt, nxt % STAGES, m0, n0, tid, smem_u32);
        cp_commit();

        const uint32_t aBase = smem_u32 + (uint32_t)(st * A_STAGE_H) * 2;
        const uint32_t bBase = smem_u32 + (uint32_t)(B_BASE_H + st * B_STAGE_H) * 2;

        #pragma unroll
        for (int ks = 0; ks < BK / 16; ks++) {
            const int ck0 = ks * 2;
            uint32_t afr[2][4];
            #pragma unroll
            for (int mt = 0; mt < 2; mt++) {
                int r = rowA[mt];
                uint32_t addr = aBase +
                    (uint32_t)(r * BK + (((ck0 + a_lc) ^ (r & 7)) << 3)) * 2;
                ldsm_x4(afr[mt][0], afr[mt][1], afr[mt][2], afr[mt][3], addr);
            }
            uint32_t bfr[8][2];
            #pragma unroll
            for (int p = 0; p < 4; p++) {
                int r = rowB[p];
                uint32_t addr = bBase +
                    (uint32_t)(r * BK + (((ck0 + b_lc) ^ (r & 7)) << 3)) * 2;
                uint32_t r0, r1, r2, r3;
                ldsm_x4(r0, r1, r2, r3, addr);
                bfr[2 * p][0] = r0;     bfr[2 * p][1] = r1;
                bfr[2 * p + 1][0] = r2; bfr[2 * p + 1][1] = r3;
            }
            #pragma unroll
            for (int mt = 0; mt < 2; mt++)
                #pragma unroll
                for (int nt = 0; nt < 8; nt++)
                    mma_f16(acc[mt][nt], afr[mt], bfr[nt]);
        }

        cp_wait<1>();
        __syncthreads();
        st++; if (st == STAGES) st = 0;
    }

    // epilogue
    const int lrow_q = lane >> 2;
    const int lcol_q = lane & 3;
    const int mrow  = m0 + wm * 32 + lrow_q;
    const int ncol0 = n0 + wn * 64 + lcol_q * 2;
    #pragma unroll
    for (int mt = 0; mt < 2; mt++) {
        #pragma unroll
        for (int nt = 0; nt < 8; nt++) {
            int r = mrow + mt * 16;
            int c = ncol0 + nt * 8;
            float2 lo = make_float2(acc[mt][nt][0], acc[mt][nt][1]);
            float2 hi = make_float2(acc[mt][nt][2], acc[mt][nt][3]);
            *reinterpret_cast<float2*>(y + (size_t)r * OUT_DIM + c)       = lo;
            *reinterpret_cast<float2*>(y + (size_t)(r + 8) * OUT_DIM + c) = hi;
        }
    }
}

extern "C" void kernel_launch(void* const* d_in, const int* in_sizes, int n_in,
                              void* d_out, int out_size) {
    const float* x      = (const float*)d_in[0];
    const float* scales = (const float*)d_in[1];
    const int*   codes  = (const int*)d_in[2];
    float*       y      = (float*)d_out;

    cudaFuncSetAttribute(gguf_hgemm4, cudaFuncAttributeMaxDynamicSharedMemorySize,
                         SMEM_BYTES);

    int ntot = NX4 + NW4;
    prepass_kernel<<<(ntot + 255) / 256, 256>>>(
        reinterpret_cast<const float4*>(x), scales,
        reinterpret_cast<const int4*>(codes));

    dim3 grid(OUT_DIM / BN, M_DIM / BM);   // (32, 32)
    gguf_hgemm4<<<grid, THREADS, SMEM_BYTES>>>(y);
}

// round 8
// speedup vs baseline: 1.1671x; 1.1671x over previous
#include <cuda_runtime.h>
#include <cuda_fp16.h>
#include <cstdint>

// y = x @ W^T,  W[o,k] = scales[o,k/32] * (codes[o,k] - 128)
// R8: R5 base (CTA 128x128, 4 warps of 64x64, cp.async 3-stage, 2 CTA/SM)
// + explicit software pipelining: double-buffered ldmatrix fragments
// (prefetch ks+1 / next-stage ks0 before current MMAs), early wait+sync
// overlapped with last MMA batch.

#define IN_DIM   4096
#define OUT_DIM  4096
#define M_DIM    4096
#define NBLK_    128

#define BM       128
#define BN       128
#define BK       64
#define STAGES   3
#define THREADS  128
#define KITERS   (IN_DIM / BK)   // 64

__device__ __half g_xh[(size_t)M_DIM * IN_DIM];
__device__ __half g_wh[(size_t)OUT_DIM * IN_DIM];

#define A_STAGE_H   (BM * BK)                     // 8192 halves (16 KB)
#define B_STAGE_H   (BN * BK)
#define B_BASE_H    (STAGES * A_STAGE_H)
#define SMEM_BYTES  ((STAGES * (A_STAGE_H + B_STAGE_H)) * 2)   // 98304

// ---------------- merged prepass ----------------
#define NX4 ((M_DIM * IN_DIM) / 4)
#define NW4 ((OUT_DIM * IN_DIM) / 4)

__global__ void prepass_kernel(const float4* __restrict__ x,
                               const float* __restrict__ scales,
                               const int4* __restrict__ codes) {
    int i = blockIdx.x * blockDim.x + threadIdx.x;
    if (i < NX4) {
        float4 v = x[i];
        __half2 h0 = __floats2half2_rn(v.x, v.y);
        __half2 h1 = __floats2half2_rn(v.z, v.w);
        uint2 u;
        u.x = *reinterpret_cast<uint32_t*>(&h0);
        u.y = *reinterpret_cast<uint32_t*>(&h1);
        reinterpret_cast<uint2*>(g_xh)[i] = u;
    } else if (i < NX4 + NW4) {
        int j = i - NX4;
        int gelt = j * 4;
        int o  = gelt >> 12;
        int kb = (gelt & 4095) >> 5;
        float s = __ldg(scales + o * NBLK_ + kb);
        int4 c = codes[j];
        __half2 h0 = __floats2half2_rn(s * (float)(c.x - 128), s * (float)(c.y - 128));
        __half2 h1 = __floats2half2_rn(s * (float)(c.z - 128), s * (float)(c.w - 128));
        uint2 u;
        u.x = *reinterpret_cast<uint32_t*>(&h0);
        u.y = *reinterpret_cast<uint32_t*>(&h1);
        reinterpret_cast<uint2*>(g_wh)[j] = u;
    }
}

// ---------------- GEMM helpers ----------------

__device__ __forceinline__ void cp_async16(uint32_t saddr, const void* g) {
    asm volatile("cp.async.cg.shared.global [%0], [%1], 16;" :: "r"(saddr), "l"(g));
}
__device__ __forceinline__ void cp_commit() {
    asm volatile("cp.async.commit_group;");
}
template <int N>
__device__ __forceinline__ void cp_wait() {
    asm volatile("cp.async.wait_group %0;" :: "n"(N));
}
__device__ __forceinline__ void ldsm_x4(uint32_t& r0, uint32_t& r1,
                                        uint32_t& r2, uint32_t& r3, uint32_t addr) {
    asm volatile("ldmatrix.sync.aligned.m8n8.x4.shared.b16 {%0,%1,%2,%3}, [%4];"
                 : "=r"(r0), "=r"(r1), "=r"(r2), "=r"(r3) : "r"(addr));
}
__device__ __forceinline__ void mma_f16(float* c, const uint32_t* a, const uint32_t* b) {
    asm volatile(
        "mma.sync.aligned.m16n8k16.row.col.f32.f16.f16.f32 "
        "{%0,%1,%2,%3}, {%4,%5,%6,%7}, {%8,%9}, {%0,%1,%2,%3};"
        : "+f"(c[0]), "+f"(c[1]), "+f"(c[2]), "+f"(c[3])
        : "r"(a[0]), "r"(a[1]), "r"(a[2]), "r"(a[3]), "r"(b[0]), "r"(b[1]));
}

__device__ __forceinline__ int tile_off(int row, int chunk) {
    return row * BK + ((chunk ^ (row & 7)) << 3);
}

__device__ __forceinline__ void load_stage(int kb, int st, int m0, int n0,
                                           int tid, uint32_t smem_u32) {
    const __half* gA = g_xh + (size_t)m0 * IN_DIM + kb * BK;
    const __half* gB = g_wh + (size_t)n0 * IN_DIM + kb * BK;
    uint32_t aBase = smem_u32 + (uint32_t)(st * A_STAGE_H) * 2;
    uint32_t bBase = smem_u32 + (uint32_t)(B_BASE_H + st * B_STAGE_H) * 2;
    #pragma unroll
    for (int it = 0; it < 8; it++) {
        int idx = tid + it * THREADS;
        int row = idx >> 3, ch = idx & 7;
        cp_async16(aBase + (uint32_t)tile_off(row, ch) * 2,
                   gA + (size_t)row * IN_DIM + ch * 8);
    }
    #pragma unroll
    for (int it = 0; it < 8; it++) {
        int idx = tid + it * THREADS;
        int row = idx >> 3, ch = idx & 7;
        cp_async16(bBase + (uint32_t)tile_off(row, ch) * 2,
                   gB + (size_t)row * IN_DIM + ch * 8);
    }
}

struct Frag {
    uint32_t a[4][4];
    uint32_t b[8][2];
};

__global__ __launch_bounds__(THREADS, 2)
void gguf_hgemm6(float* __restrict__ y) {
    extern __shared__ __half sm[];
    uint32_t smem_u32 = (uint32_t)__cvta_generic_to_shared(sm);

    const int tid  = threadIdx.x;
    const int lane = tid & 31;
    const int wid  = tid >> 5;
    const int wm   = wid >> 1;     // 0..1 -> 64 m rows
    const int wn   = wid & 1;      // 0..1 -> 64 n cols

    const int m0 = blockIdx.y * BM;
    const int n0 = blockIdx.x * BN;

    float acc[4][8][4];
    #pragma unroll
    for (int i = 0; i < 4; i++)
        #pragma unroll
        for (int j = 0; j < 8; j++)
            #pragma unroll
            for (int v = 0; v < 4; v++) acc[i][j][v] = 0.0f;

    const int a_lr = lane & 15;
    const int a_lc = lane >> 4;
    const int b_lr = (lane & 7) + ((lane >> 4) << 3);
    const int b_lc = (lane >> 3) & 1;

    int rowA[4], rowB[4];
    #pragma unroll
    for (int mt = 0; mt < 4; mt++) rowA[mt] = wm * 64 + mt * 16 + a_lr;
    #pragma unroll
    for (int p = 0; p < 4; p++)    rowB[p]  = wn * 64 + p * 16 + b_lr;

    // fragment loader for (stage base pair, ks)
    auto load_frags = [&](Frag& f, uint32_t aBase, uint32_t bBase, int ks) {
        const int ck0 = ks * 2;
        #pragma unroll
        for (int mt = 0; mt < 4; mt++) {
            int r = rowA[mt];
            uint32_t addr = aBase +
                (uint32_t)(r * BK + (((ck0 + a_lc) ^ (r & 7)) << 3)) * 2;
            ldsm_x4(f.a[mt][0], f.a[mt][1], f.a[mt][2], f.a[mt][3], addr);
        }
        #pragma unroll
        for (int p = 0; p < 4; p++) {
            int r = rowB[p];
            uint32_t addr = bBase +
                (uint32_t)(r * BK + (((ck0 + b_lc) ^ (r & 7)) << 3)) * 2;
            uint32_t r0, r1, r2, r3;
            ldsm_x4(r0, r1, r2, r3, addr);
            f.b[2 * p][0] = r0;     f.b[2 * p][1] = r1;
            f.b[2 * p + 1][0] = r2; f.b[2 * p + 1][1] = r3;
        }
    };

    auto stage_a = [&](int s) {
        return smem_u32 + (uint32_t)(s * A_STAGE_H) * 2;
    };
    auto stage_b = [&](int s) {
        return smem_u32 + (uint32_t)(B_BASE_H + s * B_STAGE_H) * 2;
    };

    // prologue
    load_stage(0, 0, m0, n0, tid, smem_u32); cp_commit();
    load_stage(1, 1, m0, n0, tid, smem_u32); cp_commit();
    cp_wait<1>();
    __syncthreads();

    Frag frag[2];
    load_frags(frag[0], stage_a(0), stage_b(0), 0);
    int fb = 0;

    int s = 0;
    for (int kb = 0; kb < KITERS; kb++) {
        const uint32_t aB = stage_a(s);
        const uint32_t bB = stage_b(s);
        const int sn = (s + 1 == STAGES) ? 0 : s + 1;

        #pragma unroll
        for (int ks = 0; ks < BK / 16; ks++) {
            const int nb = fb ^ 1;
            if (ks < BK / 16 - 1) {
                // prefetch next ks of current stage
                load_frags(frag[nb], aB, bB, ks + 1);
            } else {
                // issue next+2 stage copies, then drain: stage kb+1 ready
                int nk = kb + 2;
                if (nk < KITERS) {
                    int s2 = (s + 2 >= STAGES) ? s + 2 - STAGES : s + 2;
                    load_stage(nk, s2, m0, n0, tid, smem_u32);
                }
                cp_commit();
                cp_wait<1>();
                __syncthreads();
                if (kb + 1 < KITERS)
                    load_frags(frag[nb], stage_a(sn), stage_b(sn), 0);
            }
            // MMAs for current fragments (overlap with prefetch above)
            #pragma unroll
            for (int mt = 0; mt < 4; mt++)
                #pragma unroll
                for (int nt = 0; nt < 8; nt++)
                    mma_f16(acc[mt][nt], frag[fb].a[mt], frag[fb].b[nt]);
            fb = nb;
        }

        s = sn;
    }

    // epilogue
    const int lrow_q = lane >> 2;
    const int lcol_q = lane & 3;
    const int mrow  = m0 + wm * 64 + lrow_q;
    const int ncol0 = n0 + wn * 64 + lcol_q * 2;
    #pragma unroll
    for (int mt = 0; mt < 4; mt++) {
        #pragma unroll
        for (int nt = 0; nt < 8; nt++) {
            int r = mrow + mt * 16;
            int c = ncol0 + nt * 8;
            float2 lo = make_float2(acc[mt][nt][0], acc[mt][nt][1]);
            float2 hi = make_float2(acc[mt][nt][2], acc[mt][nt][3]);
            *reinterpret_cast<float2*>(y + (size_t)r * OUT_DIM + c)       = lo;
            *reinterpret_cast<float2*>(y + (size_t)(r + 8) * OUT_DIM + c) = hi;
        }
    }
}

extern "C" void kernel_launch(void* const* d_in, const int* in_sizes, int n_in,
                              void* d_out, int out_size) {
    const float* x      = (const float*)d_in[0];
    const float* scales = (const float*)d_in[1];
    const int*   codes  = (const int*)d_in[2];
    float*       y      = (float*)d_out;

    cudaFuncSetAttribute(gguf_hgemm6, cudaFuncAttributeMaxDynamicSharedMemorySize,
                         SMEM_BYTES);

    int ntot = NX4 + NW4;
    prepass_kernel<<<(ntot + 255) / 256, 256>>>(
        reinterpret_cast<const float4*>(x), scales,
        reinterpret_cast<const int4*>(codes));

    dim3 grid(OUT_DIM / BN, M_DIM / BM);   // (32, 32)
    gguf_hgemm6<<<grid, THREADS, SMEM_BYTES>>>(y);
}